// round 1
// baseline (speedup 1.0000x reference)
#include <cuda_runtime.h>
#include <cuda_bf16.h>
#include <cstdint>

#define T_STEPS 256
#define BATCH   16
#define HID     100
#define G4      400
#define VOCAB   30522
#define M_ROWS  4096   // T*B

// Scratch (static __device__ arrays — allocation rules forbid cudaMalloc)
__device__ float g_gx[(size_t)M_ROWS * G4];  // pre-activations gx = x@W_ih^T + b_ih + b_hh
__device__ float g_hs[(size_t)M_ROWS * HID]; // decoder hidden states (GEMM A matrix)

// ---------------------------------------------------------------------------
// Kernel 1: gx[r][j] = sum_k emb[input[r]][k] * W_ih[j][k] + b_ih[j] + b_hh[j]
// One CTA handles 32 rows (r) x all 400 gates (j). x rows cached in smem
// (broadcast reads), W_ih streamed from L2 per-thread.
// ---------------------------------------------------------------------------
__global__ __launch_bounds__(400) void gx_kernel(
        const int* __restrict__ input,
        const float* __restrict__ emb,
        const float* __restrict__ W_ih,
        const float* __restrict__ b_ih,
        const float* __restrict__ b_hh) {
    __shared__ float4 xs[32 * 25];   // 32 rows x 100 floats (as float4)
    __shared__ int    idx[32];
    const int tid = threadIdx.x;
    const int r0  = blockIdx.x * 32;

    if (tid < 32) idx[tid] = input[r0 + tid];
    __syncthreads();
    for (int p = tid; p < 32 * 25; p += 400) {
        int i = p / 25, k4 = p % 25;
        xs[i * 25 + k4] = ((const float4*)(emb + (size_t)idx[i] * HID))[k4];
    }
    __syncthreads();

    const int j = tid;  // 0..399
    float bias = b_ih[j] + b_hh[j];
    float acc[32];
    #pragma unroll
    for (int i = 0; i < 32; i++) acc[i] = bias;

    const float4* w4 = (const float4*)(W_ih + (size_t)j * HID);
    for (int k4 = 0; k4 < 25; k4++) {
        float4 w = w4[k4];
        #pragma unroll
        for (int i = 0; i < 32; i++) {
            float4 x = xs[i * 25 + k4];
            acc[i] += w.x * x.x + w.y * x.y + w.z * x.z + w.w * x.w;
        }
    }
    #pragma unroll 4
    for (int i = 0; i < 32; i++)
        g_gx[(size_t)(r0 + i) * G4 + j] = acc[i];
}

// ---------------------------------------------------------------------------
// Kernel 2: LSTM recurrence. One CTA per batch element (16 CTAs).
// Thread j (<400) owns gate row j: W_hh[j][0..99] held in registers as 50
// packed f32x2 values; the recurrent dot uses fma.rn.f32x2 (2x FFMA rate).
// h lives in smem; c lives in registers of threads j<100.
// ---------------------------------------------------------------------------
__device__ __forceinline__ void fma2(unsigned long long& acc,
                                     unsigned long long a,
                                     unsigned long long b) {
    asm("fma.rn.f32x2 %0, %1, %2, %0;" : "+l"(acc) : "l"(a), "l"(b));
}
__device__ __forceinline__ float unpack_sum(unsigned long long a) {
    float lo, hi;
    asm("mov.b64 {%0, %1}, %2;" : "=f"(lo), "=f"(hi) : "l"(a));
    return lo + hi;
}

__global__ __launch_bounds__(416, 1) void lstm_kernel(const float* __restrict__ W_hh) {
    __shared__ __align__(16) float h_s[HID];
    __shared__ float acts[G4];
    const int j = threadIdx.x;
    const int b = blockIdx.x;

    unsigned long long w2[50];
    if (j < G4) {
        const unsigned long long* wg =
            (const unsigned long long*)(W_hh + (size_t)j * HID);
        #pragma unroll
        for (int k = 0; k < 50; k++) w2[k] = wg[k];
    }
    if (j < HID) h_s[j] = 0.f;
    float c = 0.f;
    float gcur = (j < G4) ? g_gx[(size_t)b * G4 + j] : 0.f;  // t=0
    __syncthreads();

    for (int t = 0; t < T_STEPS; t++) {
        // prefetch next step's pre-activation (hides DRAM/L2 latency)
        float gnext = 0.f;
        if (t + 1 < T_STEPS && j < G4)
            gnext = g_gx[((size_t)(t + 1) * BATCH + b) * G4 + j];

        float a = 0.f;
        if (j < G4) {
            const unsigned long long* h2 = (const unsigned long long*)h_s;
            unsigned long long acc0 = 0ull, acc1 = 0ull;  // {+0f,+0f}
            #pragma unroll
            for (int k = 0; k < 50; k += 2) {
                fma2(acc0, w2[k],     h2[k]);
                fma2(acc1, w2[k + 1], h2[k + 1]);
            }
            float d = gcur + unpack_sum(acc0) + unpack_sum(acc1);
            if (j >= 2 * HID && j < 3 * HID) a = tanhf(d);            // g gate
            else                             a = 1.f / (1.f + expf(-d)); // i,f,o
            acts[j] = a;
        }
        __syncthreads();  // all h_s reads done; acts visible

        if (j < HID) {
            float ig = acts[j], fg = acts[HID + j];
            float gg = acts[2 * HID + j], og = acts[3 * HID + j];
            c = fg * c + ig * gg;
            float hn = og * tanhf(c);
            h_s[j] = hn;
            g_hs[((size_t)t * BATCH + b) * HID + j] = hn;
        }
        __syncthreads();  // new h_s visible for next iteration
        gcur = gnext;
    }
}

// ---------------------------------------------------------------------------
// Kernel 3: out[r][v] = dec_out[r] . out_W[v] + out_b[v]
// M=4096, N=30522, K=100 (padded to 112 = 7 x k16).
// Split-precision bf16: x = hi + lo; product ~ hi*hi + hi*lo + lo*hi (3 MMAs)
// -> ~2^-16 relative error, fp32 accumulate.
// CTA tile 128x64, 8 warps in 4(M)x2(N), warp tile 32x32.
// ---------------------------------------------------------------------------
#define BM 128
#define BN 64
#define KP 112
#define GEMM_SMEM ((2 * BM * KP + 2 * BN * KP) * 2)  // 86016 bytes

__device__ __forceinline__ void mma16816(float* c, const uint32_t* a,
                                         uint32_t b0, uint32_t b1) {
    asm volatile(
        "mma.sync.aligned.m16n8k16.row.col.f32.bf16.bf16.f32 "
        "{%0,%1,%2,%3},{%4,%5,%6,%7},{%8,%9},{%0,%1,%2,%3};\n"
        : "+f"(c[0]), "+f"(c[1]), "+f"(c[2]), "+f"(c[3])
        : "r"(a[0]), "r"(a[1]), "r"(a[2]), "r"(a[3]), "r"(b0), "r"(b1));
}

__global__ __launch_bounds__(256) void gemm_kernel(
        const float* __restrict__ out_W,
        const float* __restrict__ out_b,
        float* __restrict__ out) {
    extern __shared__ __nv_bfloat16 sm[];
    __nv_bfloat16* Ahi = sm;                 // [BM][KP]
    __nv_bfloat16* Alo = Ahi + BM * KP;
    __nv_bfloat16* Bhi = Alo + BM * KP;      // [BN][KP] (n-major == out_W layout)
    __nv_bfloat16* Blo = Bhi + BN * KP;

    const int tid = threadIdx.x;
    const int m0  = blockIdx.y * BM;
    const int n0  = blockIdx.x * BN;

    // zero-fill (covers the K padding region [100,112))
    {
        uint32_t* s32 = (uint32_t*)sm;
        const int tot32 = GEMM_SMEM / 4;
        for (int p = tid; p < tot32; p += 256) s32[p] = 0u;
    }
    __syncthreads();

    // load + split A (dec hidden states, fp32)
    for (int p = tid; p < BM * HID; p += 256) {
        int i = p / HID, k = p % HID;
        float v = g_hs[(size_t)(m0 + i) * HID + k];
        __nv_bfloat16 hi = __float2bfloat16(v);
        float rem = v - __bfloat162float(hi);
        Ahi[i * KP + k] = hi;
        Alo[i * KP + k] = __float2bfloat16(rem);
    }
    // load + split B (out_W rows), zero-padded past VOCAB
    for (int p = tid; p < BN * HID; p += 256) {
        int n = p / HID, k = p % HID;
        int col = n0 + n;
        float v = (col < VOCAB) ? out_W[(size_t)col * HID + k] : 0.f;
        __nv_bfloat16 hi = __float2bfloat16(v);
        float rem = v - __bfloat162float(hi);
        Bhi[n * KP + k] = hi;
        Blo[n * KP + k] = __float2bfloat16(rem);
    }
    __syncthreads();

    const int lane = tid & 31, wp = tid >> 5;
    const int wm = wp >> 1, wn = wp & 1;      // 4 x 2 warp grid
    const int gid = lane >> 2, tig = lane & 3;

    float acc[2][4][4];
    #pragma unroll
    for (int mb = 0; mb < 2; mb++)
        #pragma unroll
        for (int nb = 0; nb < 4; nb++)
            #pragma unroll
            for (int q = 0; q < 4; q++) acc[mb][nb][q] = 0.f;

    const uint32_t* A32h = (const uint32_t*)Ahi;
    const uint32_t* A32l = (const uint32_t*)Alo;
    const uint32_t* B32h = (const uint32_t*)Bhi;
    const uint32_t* B32l = (const uint32_t*)Blo;

    #pragma unroll
    for (int ks = 0; ks < 7; ks++) {
        const int k0 = ks * 16;
        uint32_t ah[2][4], al[2][4];
        #pragma unroll
        for (int mb = 0; mb < 2; mb++) {
            int row  = wm * 32 + mb * 16 + gid;
            int base = (row * KP + k0 + tig * 2) >> 1;     // u32 index
            ah[mb][0] = A32h[base];       al[mb][0] = A32l[base];
            ah[mb][1] = A32h[base + 448]; al[mb][1] = A32l[base + 448]; // row+8
            ah[mb][2] = A32h[base + 4];   al[mb][2] = A32l[base + 4];   // k+8
            ah[mb][3] = A32h[base + 452]; al[mb][3] = A32l[base + 452];
        }
        #pragma unroll
        for (int nb = 0; nb < 4; nb++) {
            int nrow  = wn * 32 + nb * 8 + gid;
            int bbase = (nrow * KP + k0 + tig * 2) >> 1;
            uint32_t bh0 = B32h[bbase], bh1 = B32h[bbase + 4];
            uint32_t bl0 = B32l[bbase], bl1 = B32l[bbase + 4];
            #pragma unroll
            for (int mb = 0; mb < 2; mb++) {
                mma16816(acc[mb][nb], ah[mb], bh0, bh1);  // hi*hi
                mma16816(acc[mb][nb], ah[mb], bl0, bl1);  // hi*lo
                mma16816(acc[mb][nb], al[mb], bh0, bh1);  // lo*hi
            }
        }
    }

    // epilogue: + out_b, fp32 store (float2, 8B aligned: VOCAB even, col even)
    #pragma unroll
    for (int nb = 0; nb < 4; nb++) {
        int col = n0 + wn * 32 + nb * 8 + tig * 2;
        if (col >= VOCAB) continue;
        float bb0 = out_b[col], bb1 = out_b[col + 1];
        #pragma unroll
        for (int mb = 0; mb < 2; mb++) {
            int row = m0 + wm * 32 + mb * 16 + gid;
            float2 v0 = make_float2(acc[mb][nb][0] + bb0, acc[mb][nb][1] + bb1);
            float2 v1 = make_float2(acc[mb][nb][2] + bb0, acc[mb][nb][3] + bb1);
            *(float2*)(out + (size_t)row * VOCAB + col)       = v0;
            *(float2*)(out + (size_t)(row + 8) * VOCAB + col) = v1;
        }
    }
}

// ---------------------------------------------------------------------------
// Launch: encoder is dead code in the reference -> skipped entirely.
// Inputs (metadata order): 0 input(int32), 1 emb, 2..5 enc_* (unused),
// 6 dec_W_ih, 7 dec_W_hh, 8 dec_b_ih, 9 dec_b_hh, 10 out_W, 11 out_b.
// ---------------------------------------------------------------------------
extern "C" void kernel_launch(void* const* d_in, const int* in_sizes, int n_in,
                              void* d_out, int out_size) {
    (void)in_sizes; (void)n_in; (void)out_size;
    const int*   input = (const int*)d_in[0];
    const float* emb   = (const float*)d_in[1];
    const float* dWih  = (const float*)d_in[6];
    const float* dWhh  = (const float*)d_in[7];
    const float* dbih  = (const float*)d_in[8];
    const float* dbhh  = (const float*)d_in[9];
    const float* outW  = (const float*)d_in[10];
    const float* outb  = (const float*)d_in[11];
    float* out = (float*)d_out;

    gx_kernel<<<M_ROWS / 32, 400>>>(input, emb, dWih, dbih, dbhh);
    lstm_kernel<<<BATCH, 416>>>(dWhh);

    cudaFuncSetAttribute(gemm_kernel,
                         cudaFuncAttributeMaxDynamicSharedMemorySize, GEMM_SMEM);
    gemm_kernel<<<dim3((VOCAB + BN - 1) / BN, M_ROWS / BM), 256, GEMM_SMEM>>>(
        outW, outb, out);
}

// round 3
// speedup vs baseline: 1.7950x; 1.7950x over previous
#include <cuda_runtime.h>
#include <cuda_bf16.h>
#include <cstdint>

#define T_STEPS 256
#define BATCH   16
#define HID     100
#define G4      400
#define VOCAB   30522
#define M_ROWS  4096   // T*B

// GEMM tiling
#define KP    112              // K padded to 7 x 16
#define MT    128
#define NT    128
#define NBLK  239              // ceil(VOCAB/128)
#define NPAD  (NBLK * 128)     // 30592
#define NSEG  (NBLK * 4)       // 956 segments (n-block x m-chunk of 8)
#define ROWB  240              // smem row bytes (120 bf16, pad for bank-free LDS)
#define ROWW  60               // smem row stride in u32 words

// ---------------------------------------------------------------------------
// Device scratch
// ---------------------------------------------------------------------------
__device__ float g_gx[(size_t)M_ROWS * G4];
__device__ float g_hs[(size_t)M_ROWS * HID];
__device__ __align__(16) __nv_bfloat16 gA_hi[(size_t)M_ROWS * KP];
__device__ __align__(16) __nv_bfloat16 gA_lo[(size_t)M_ROWS * KP];
__device__ __align__(16) __nv_bfloat16 gW_hi[(size_t)NPAD * KP];
__device__ __align__(16) __nv_bfloat16 gW_lo[(size_t)NPAD * KP];
__device__ int g_counter;

// ---------------------------------------------------------------------------
// Kernel 1: gx = emb[input] @ W_ih^T + b_ih + b_hh
// ---------------------------------------------------------------------------
__global__ __launch_bounds__(400) void gx_kernel(
        const int* __restrict__ input,
        const float* __restrict__ emb,
        const float* __restrict__ W_ih,
        const float* __restrict__ b_ih,
        const float* __restrict__ b_hh) {
    __shared__ float4 xs[32 * 25];
    __shared__ int    idx[32];
    const int tid = threadIdx.x;
    const int r0  = blockIdx.x * 32;

    if (tid < 32) idx[tid] = input[r0 + tid];
    __syncthreads();
    for (int p = tid; p < 32 * 25; p += 400) {
        int i = p / 25, k4 = p % 25;
        xs[i * 25 + k4] = ((const float4*)(emb + (size_t)idx[i] * HID))[k4];
    }
    __syncthreads();

    const int j = tid;
    float bias = b_ih[j] + b_hh[j];
    float acc[32];
    #pragma unroll
    for (int i = 0; i < 32; i++) acc[i] = bias;

    const float4* w4 = (const float4*)(W_ih + (size_t)j * HID);
    for (int k4 = 0; k4 < 25; k4++) {
        float4 w = w4[k4];
        #pragma unroll
        for (int i = 0; i < 32; i++) {
            float4 x = xs[i * 25 + k4];
            acc[i] += w.x * x.x + w.y * x.y + w.z * x.z + w.w * x.w;
        }
    }
    #pragma unroll 4
    for (int i = 0; i < 32; i++)
        g_gx[(size_t)(r0 + i) * G4 + j] = acc[i];
}

// ---------------------------------------------------------------------------
// Kernel 2: LSTM recurrence (one CTA per batch element)
// ---------------------------------------------------------------------------
__device__ __forceinline__ void fma2(unsigned long long& acc,
                                     unsigned long long a,
                                     unsigned long long b) {
    asm("fma.rn.f32x2 %0, %1, %2, %0;" : "+l"(acc) : "l"(a), "l"(b));
}
__device__ __forceinline__ float unpack_sum(unsigned long long a) {
    float lo, hi;
    asm("mov.b64 {%0, %1}, %2;" : "=f"(lo), "=f"(hi) : "l"(a));
    return lo + hi;
}

__global__ __launch_bounds__(416, 1) void lstm_kernel(const float* __restrict__ W_hh) {
    __shared__ __align__(16) float h_s[HID];
    __shared__ float acts[G4];
    const int j = threadIdx.x;
    const int b = blockIdx.x;

    unsigned long long w2[50];
    if (j < G4) {
        const unsigned long long* wg =
            (const unsigned long long*)(W_hh + (size_t)j * HID);
        #pragma unroll
        for (int k = 0; k < 50; k++) w2[k] = wg[k];
    }
    if (j < HID) h_s[j] = 0.f;
    float c = 0.f;
    float gcur = (j < G4) ? g_gx[(size_t)b * G4 + j] : 0.f;
    __syncthreads();

    for (int t = 0; t < T_STEPS; t++) {
        float gnext = 0.f;
        if (t + 1 < T_STEPS && j < G4)
            gnext = g_gx[((size_t)(t + 1) * BATCH + b) * G4 + j];

        float a = 0.f;
        if (j < G4) {
            const unsigned long long* h2 = (const unsigned long long*)h_s;
            unsigned long long acc0 = 0ull, acc1 = 0ull;
            #pragma unroll
            for (int k = 0; k < 50; k += 2) {
                fma2(acc0, w2[k],     h2[k]);
                fma2(acc1, w2[k + 1], h2[k + 1]);
            }
            float d = gcur + unpack_sum(acc0) + unpack_sum(acc1);
            if (j >= 2 * HID && j < 3 * HID) a = tanhf(d);
            else                             a = 1.f / (1.f + expf(-d));
            acts[j] = a;
        }
        __syncthreads();

        if (j < HID) {
            float ig = acts[j], fg = acts[HID + j];
            float gg = acts[2 * HID + j], og = acts[3 * HID + j];
            c = fg * c + ig * gg;
            float hn = og * tanhf(c);
            h_s[j] = hn;
            g_hs[((size_t)t * BATCH + b) * HID + j] = hn;
        }
        __syncthreads();
        gcur = gnext;
    }
}

// ---------------------------------------------------------------------------
// Kernel 2.5: split fp32 -> (hi, lo) bf16, K padded to 112.
// One unit = 8 consecutive k of one row. Also resets the work-steal counter.
// ---------------------------------------------------------------------------
#define A_UNITS (M_ROWS * 14)          // 57344
#define W_UNITS (NPAD * 14)            // 428288
#define S_UNITS (A_UNITS + W_UNITS)    // 485632

__global__ __launch_bounds__(256) void split_kernel(const float* __restrict__ out_W) {
    if (blockIdx.x == 0 && threadIdx.x == 0) g_counter = 0;
    const int u = blockIdx.x * 256 + threadIdx.x;
    if (u >= S_UNITS) return;

    float v[8];
    size_t dst;
    __nv_bfloat16 *dhi, *dlo;
    if (u < A_UNITS) {
        int row = u / 14, k0 = (u % 14) * 8;
        #pragma unroll
        for (int i = 0; i < 8; i++) {
            int k = k0 + i;
            v[i] = (k < HID) ? g_hs[(size_t)row * HID + k] : 0.f;
        }
        dst = (size_t)row * KP + k0; dhi = gA_hi; dlo = gA_lo;
    } else {
        int w = u - A_UNITS;
        int row = w / 14, k0 = (w % 14) * 8;
        #pragma unroll
        for (int i = 0; i < 8; i++) {
            int k = k0 + i;
            v[i] = (row < VOCAB && k < HID) ? out_W[(size_t)row * HID + k] : 0.f;
        }
        dst = (size_t)row * KP + k0; dhi = gW_hi; dlo = gW_lo;
    }
    uint32_t ph[4], pl[4];
    #pragma unroll
    for (int jj = 0; jj < 4; jj++) {
        __nv_bfloat16 h0 = __float2bfloat16(v[2*jj]);
        __nv_bfloat16 h1 = __float2bfloat16(v[2*jj+1]);
        __nv_bfloat16 l0 = __float2bfloat16(v[2*jj]   - __bfloat162float(h0));
        __nv_bfloat16 l1 = __float2bfloat16(v[2*jj+1] - __bfloat162float(h1));
        ph[jj] = (uint32_t)__bfloat16_as_ushort(h0) |
                 ((uint32_t)__bfloat16_as_ushort(h1) << 16);
        pl[jj] = (uint32_t)__bfloat16_as_ushort(l0) |
                 ((uint32_t)__bfloat16_as_ushort(l1) << 16);
    }
    *(uint4*)(dhi + dst) = make_uint4(ph[0], ph[1], ph[2], ph[3]);
    *(uint4*)(dlo + dst) = make_uint4(pl[0], pl[1], pl[2], pl[3]);
}

// ---------------------------------------------------------------------------
// Kernel 3: persistent HMMA GEMM. 128x128 tiles, B-stationary segments,
// cp.async double-buffered A, split bf16 (3 MMAs per k-step).
// 8 warps in 2(M) x 4(N); warp tile 64x32.
// ---------------------------------------------------------------------------
// smem byte map
#define SM_BIAS 0                       // 128 floats
#define SM_SEG  512
#define SM_A    1024                    // 2 x 61440 (hi at +0, lo at +30720)
#define SM_B    (SM_A + 2 * 61440)      // 123904 (hi +0, lo +30720)
#define SM_TOT  (SM_B + 61440)          // 185344

__device__ __forceinline__ void cp16(uint32_t dst, const void* src) {
    asm volatile("cp.async.ca.shared.global [%0], [%1], 16;" :: "r"(dst), "l"(src));
}
__device__ __forceinline__ uint32_t smem_u32(const void* p) {
    uint32_t a;
    asm("{ .reg .u64 t; cvta.to.shared.u64 t, %1; cvt.u32.u64 %0, t; }"
        : "=r"(a) : "l"(p));
    return a;
}
__device__ __forceinline__ void mma16816(float* c, const uint32_t* a,
                                         uint32_t b0, uint32_t b1) {
    asm volatile(
        "mma.sync.aligned.m16n8k16.row.col.f32.bf16.bf16.f32 "
        "{%0,%1,%2,%3},{%4,%5,%6,%7},{%8,%9},{%0,%1,%2,%3};\n"
        : "+f"(c[0]), "+f"(c[1]), "+f"(c[2]), "+f"(c[3])
        : "r"(a[0]), "r"(a[1]), "r"(a[2]), "r"(a[3]), "r"(b0), "r"(b1));
}

__global__ __launch_bounds__(256, 1) void gemm_kernel(
        const float* __restrict__ out_b, float* __restrict__ out) {
    extern __shared__ char sm[];
    const uint32_t sb  = smem_u32(sm);
    const int tid  = threadIdx.x;
    const int wid  = tid >> 5, lane = tid & 31;
    const int wm   = wid >> 2, wn = wid & 3;     // 2 x 4 warp grid
    const int gid  = lane >> 2, tig = lane & 3;

    for (;;) {
        if (tid == 0) *(int*)(sm + SM_SEG) = atomicAdd(&g_counter, 1);
        __syncthreads();
        const int seg = *(const int*)(sm + SM_SEG);
        if (seg >= NSEG) break;
        const int n0  = (seg >> 2) * NT;
        const int mt0 = (seg & 3) * 8;

        // ---- bias
        {
            int c = n0 + tid;
            if (tid < 128)
                ((float*)(sm + SM_BIAS))[tid] = (c < VOCAB) ? out_b[c] : 0.f;
        }
        // ---- cp.async B (hi+lo) and A tile 0
        {
            const char* srcs[2] = { (const char*)(gW_hi + (size_t)n0 * KP),
                                    (const char*)(gW_lo + (size_t)n0 * KP) };
            #pragma unroll 2
            for (int e = tid; e < 3584; e += 256) {
                int arr = e >= 1792;
                int r = (e - arr * 1792) / 14, c = e % 14;
                cp16(sb + SM_B + arr * 30720 + r * ROWB + c * 16,
                     srcs[arr] + (size_t)r * (KP * 2) + c * 16);
            }
            const int m0 = mt0 * MT;
            const char* srca[2] = { (const char*)(gA_hi + (size_t)m0 * KP),
                                    (const char*)(gA_lo + (size_t)m0 * KP) };
            #pragma unroll 2
            for (int e = tid; e < 3584; e += 256) {
                int arr = e >= 1792;
                int r = (e - arr * 1792) / 14, c = e % 14;
                cp16(sb + SM_A + arr * 30720 + r * ROWB + c * 16,
                     srca[arr] + (size_t)r * (KP * 2) + c * 16);
            }
            asm volatile("cp.async.commit_group;");
            asm volatile("cp.async.wait_group 0;");
        }
        __syncthreads();

        #pragma unroll 1
        for (int it = 0; it < 8; it++) {
            // prefetch next A tile into the other buffer
            if (it < 7) {
                const int m1 = (mt0 + it + 1) * MT;
                const uint32_t abase = sb + SM_A + ((it + 1) & 1) * 61440;
                const char* srca[2] = { (const char*)(gA_hi + (size_t)m1 * KP),
                                        (const char*)(gA_lo + (size_t)m1 * KP) };
                #pragma unroll 2
                for (int e = tid; e < 3584; e += 256) {
                    int arr = e >= 1792;
                    int r = (e - arr * 1792) / 14, c = e % 14;
                    cp16(abase + arr * 30720 + r * ROWB + c * 16,
                         srca[arr] + (size_t)r * (KP * 2) + c * 16);
                }
                asm volatile("cp.async.commit_group;");
            }

            // ---- compute tile from buffer (it & 1)
            const uint32_t* A32 = (const uint32_t*)(sm + SM_A + (it & 1) * 61440);
            const uint32_t* B32 = (const uint32_t*)(sm + SM_B);

            float acc[4][4][4];
            #pragma unroll
            for (int mb = 0; mb < 4; mb++)
                #pragma unroll
                for (int nb = 0; nb < 4; nb++)
                    #pragma unroll
                    for (int q = 0; q < 4; q++) acc[mb][nb][q] = 0.f;

            #pragma unroll 1
            for (int ks = 0; ks < 7; ks++) {
                uint32_t ah[4][4], al[4][4];
                #pragma unroll
                for (int mb = 0; mb < 4; mb++) {
                    int w = (wm * 64 + mb * 16 + gid) * ROWW + ks * 8 + tig;
                    ah[mb][0] = A32[w];
                    ah[mb][1] = A32[w + 8 * ROWW];
                    ah[mb][2] = A32[w + 4];
                    ah[mb][3] = A32[w + 8 * ROWW + 4];
                    al[mb][0] = A32[w + 7680];
                    al[mb][1] = A32[w + 7680 + 8 * ROWW];
                    al[mb][2] = A32[w + 7680 + 4];
                    al[mb][3] = A32[w + 7680 + 8 * ROWW + 4];
                }
                #pragma unroll
                for (int nb = 0; nb < 4; nb++) {
                    int w = (wn * 32 + nb * 8 + gid) * ROWW + ks * 8 + tig;
                    uint32_t bh0 = B32[w],        bh1 = B32[w + 4];
                    uint32_t bl0 = B32[w + 7680], bl1 = B32[w + 7680 + 4];
                    #pragma unroll
                    for (int mb = 0; mb < 4; mb++) {
                        mma16816(acc[mb][nb], ah[mb], bh0, bh1);
                        mma16816(acc[mb][nb], ah[mb], bl0, bl1);
                        mma16816(acc[mb][nb], al[mb], bh0, bh1);
                    }
                }
            }

            // ---- epilogue: direct register stores, float2
            const int m0 = (mt0 + it) * MT;
            const float* biasS = (const float*)(sm + SM_BIAS);
            #pragma unroll
            for (int nb = 0; nb < 4; nb++) {
                int cl  = wn * 32 + nb * 8 + tig * 2;
                int col = n0 + cl;
                if (col < VOCAB) {
                    float b0 = biasS[cl], b1 = biasS[cl + 1];
                    #pragma unroll
                    for (int mb = 0; mb < 4; mb++) {
                        int row = m0 + wm * 64 + mb * 16 + gid;
                        *(float2*)(out + (size_t)row * VOCAB + col) =
                            make_float2(acc[mb][nb][0] + b0, acc[mb][nb][1] + b1);
                        *(float2*)(out + (size_t)(row + 8) * VOCAB + col) =
                            make_float2(acc[mb][nb][2] + b0, acc[mb][nb][3] + b1);
                    }
                }
            }

            if (it < 7) asm volatile("cp.async.wait_group 0;");
            __syncthreads();
        }
    }
}

// ---------------------------------------------------------------------------
// Launch. Inputs: 0 input, 1 emb, 2..5 enc_* (dead), 6 dec_W_ih, 7 dec_W_hh,
// 8 dec_b_ih, 9 dec_b_hh, 10 out_W, 11 out_b.
// ---------------------------------------------------------------------------
extern "C" void kernel_launch(void* const* d_in, const int* in_sizes, int n_in,
                              void* d_out, int out_size) {
    (void)in_sizes; (void)n_in; (void)out_size;
    const int*   input = (const int*)d_in[0];
    const float* emb   = (const float*)d_in[1];
    const float* dWih  = (const float*)d_in[6];
    const float* dWhh  = (const float*)d_in[7];
    const float* dbih  = (const float*)d_in[8];
    const float* dbhh  = (const float*)d_in[9];
    const float* outW  = (const float*)d_in[10];
    const float* outb  = (const float*)d_in[11];
    float* out = (float*)d_out;

    gx_kernel<<<M_ROWS / 32, 400>>>(input, emb, dWih, dbih, dbhh);
    lstm_kernel<<<BATCH, 416>>>(dWhh);
    split_kernel<<<(S_UNITS + 255) / 256, 256>>>(outW);

    cudaFuncSetAttribute(gemm_kernel,
                         cudaFuncAttributeMaxDynamicSharedMemorySize, SM_TOT);
    gemm_kernel<<<148, 256, SM_TOT>>>(outb, out);
}

// round 4
// speedup vs baseline: 2.2216x; 1.2376x over previous
#include <cuda_runtime.h>
#include <cuda_fp16.h>
#include <cstdint>

#define T_STEPS 256
#define BATCH   16
#define HID     100
#define G4      400
#define VOCAB   30522
#define M_ROWS  4096   // T*B
#define KP      112    // K padded to 7 x 16

// Vocab GEMM tiling
#define MT    64
#define NT    192
#define NBLK  159              // ceil(VOCAB/192)
#define NPAD  (NBLK * NT)      // 30528
#define SEG_M 4                // m-tiles (64 rows) per stolen segment
#define NSEG  (NBLK * 16)      // 2544
#define ROWB  240              // smem row bytes (112 fp16 = 224B, pad to 240)
#define ROWW  60               // row stride in u32 words

// gx GEMM tiling
#define GXM   128
#define GXN   224              // 400 padded to 448 = 2 blocks of 224

// ---------------------------------------------------------------------------
// Device scratch
// ---------------------------------------------------------------------------
__device__ float g_gx[(size_t)M_ROWS * G4];
__device__ float g_hs[(size_t)M_ROWS * HID];
__device__ __align__(16) __half gA_hi[(size_t)M_ROWS * KP];
__device__ __align__(16) __half gA_lo[(size_t)M_ROWS * KP];
__device__ __align__(16) __half gW_hi[(size_t)NPAD * KP];   // vocab W: hi only
__device__ __align__(16) __half gE_hi[(size_t)M_ROWS * KP]; // gathered embeddings
__device__ __align__(16) __half gE_lo[(size_t)M_ROWS * KP];
__device__ __align__(16) __half gWih_hi[(size_t)448 * KP];
__device__ __align__(16) __half gWih_lo[(size_t)448 * KP];
__device__ int g_counter;

// ---------------------------------------------------------------------------
// helpers
// ---------------------------------------------------------------------------
__device__ __forceinline__ uint32_t smem_u32(const void* p) {
    uint32_t a;
    asm("{ .reg .u64 t; cvta.to.shared.u64 t, %1; cvt.u32.u64 %0, t; }"
        : "=r"(a) : "l"(p));
    return a;
}
__device__ __forceinline__ void cp16(uint32_t dst, const void* src) {
    asm volatile("cp.async.ca.shared.global [%0], [%1], 16;" :: "r"(dst), "l"(src));
}
__device__ __forceinline__ void mma_fp16(float* c, const uint32_t* a,
                                         uint32_t b0, uint32_t b1) {
    asm volatile(
        "mma.sync.aligned.m16n8k16.row.col.f32.f16.f16.f32 "
        "{%0,%1,%2,%3},{%4,%5,%6,%7},{%8,%9},{%0,%1,%2,%3};\n"
        : "+f"(c[0]), "+f"(c[1]), "+f"(c[2]), "+f"(c[3])
        : "r"(a[0]), "r"(a[1]), "r"(a[2]), "r"(a[3]), "r"(b0), "r"(b1));
}
// split 8 fp32 -> packed half2 hi[4] (and lo[4])
__device__ __forceinline__ void split8(const float* v, uint32_t* ph, uint32_t* pl) {
    #pragma unroll
    for (int j = 0; j < 4; j++) {
        __half h0 = __float2half_rn(v[2*j]);
        __half h1 = __float2half_rn(v[2*j+1]);
        __half l0 = __float2half_rn(v[2*j]   - __half2float(h0));
        __half l1 = __float2half_rn(v[2*j+1] - __half2float(h1));
        ph[j] = (uint32_t)__half_as_ushort(h0) | ((uint32_t)__half_as_ushort(h1) << 16);
        pl[j] = (uint32_t)__half_as_ushort(l0) | ((uint32_t)__half_as_ushort(l1) << 16);
    }
}

// ---------------------------------------------------------------------------
// Kernel 0: presplit. Units of 8 k-values:
//  [0, U_E)            : gather emb[input[row]] -> gE hi/lo
//  [U_E, U_E+U_WIH)    : dec_W_ih -> gWih hi/lo  (rows padded to 448)
//  [.., +U_W)          : out_W -> gW hi only     (rows padded to NPAD)
// ---------------------------------------------------------------------------
#define U_E   (M_ROWS * 14)     // 57344
#define U_WIH (448 * 14)        // 6272
#define U_W   (NPAD * 14)       // 427392
#define U_TOT (U_E + U_WIH + U_W)  // 491008 = 1918 * 256

__global__ __launch_bounds__(256) void presplit_kernel(
        const int* __restrict__ input, const float* __restrict__ emb,
        const float* __restrict__ dec_W_ih, const float* __restrict__ out_W) {
    const int u = blockIdx.x * 256 + threadIdx.x;
    float v[8];
    uint32_t ph[4], pl[4];

    if (u < U_E) {
        int row = u / 14, k0 = (u % 14) * 8;
        const float* src = emb + (size_t)input[row] * HID;
        #pragma unroll
        for (int i = 0; i < 8; i++) {
            int k = k0 + i;
            v[i] = (k < HID) ? src[k] : 0.f;
        }
        split8(v, ph, pl);
        size_t d = (size_t)row * KP + k0;
        *(uint4*)(gE_hi + d) = make_uint4(ph[0], ph[1], ph[2], ph[3]);
        *(uint4*)(gE_lo + d) = make_uint4(pl[0], pl[1], pl[2], pl[3]);
    } else if (u < U_E + U_WIH) {
        int w = u - U_E;
        int row = w / 14, k0 = (w % 14) * 8;
        #pragma unroll
        for (int i = 0; i < 8; i++) {
            int k = k0 + i;
            v[i] = (row < G4 && k < HID) ? dec_W_ih[(size_t)row * HID + k] : 0.f;
        }
        split8(v, ph, pl);
        size_t d = (size_t)row * KP + k0;
        *(uint4*)(gWih_hi + d) = make_uint4(ph[0], ph[1], ph[2], ph[3]);
        *(uint4*)(gWih_lo + d) = make_uint4(pl[0], pl[1], pl[2], pl[3]);
    } else {
        int w = u - U_E - U_WIH;
        int row = w / 14, k0 = (w % 14) * 8;
        #pragma unroll
        for (int i = 0; i < 8; i++) {
            int k = k0 + i;
            v[i] = (row < VOCAB && k < HID) ? out_W[(size_t)row * HID + k] : 0.f;
        }
        #pragma unroll
        for (int j = 0; j < 4; j++) {
            __half h0 = __float2half_rn(v[2*j]);
            __half h1 = __float2half_rn(v[2*j+1]);
            ph[j] = (uint32_t)__half_as_ushort(h0) |
                    ((uint32_t)__half_as_ushort(h1) << 16);
        }
        *(uint4*)(gW_hi + (size_t)row * KP + k0) =
            make_uint4(ph[0], ph[1], ph[2], ph[3]);
    }
}

// ---------------------------------------------------------------------------
// Kernel 1: gx via HMMA. g_gx[r][j] = E[r]·Wih[j] + b_ih[j] + b_hh[j]
// 3-term split (exact to 2^-22). Grid 64: 32 m-tiles x 2 n-blocks.
// 8 warps 2(M)x4(N), warp tile 64x56.
// ---------------------------------------------------------------------------
#define SMX_BIAS 0
#define SMX_A    1024                        // hi 30720, lo +30720
#define SMX_B    (SMX_A + 2 * GXM * ROWB)    // 62464: hi 53760, lo +53760
#define SMX_TOT  (SMX_B + 2 * GXN * ROWB)    // 169984

__global__ __launch_bounds__(256, 1) void gx_mma_kernel(
        const float* __restrict__ b_ih, const float* __restrict__ b_hh) {
    extern __shared__ char sm[];
    const uint32_t sb = smem_u32(sm);
    const int tid = threadIdx.x;
    const int nblk = blockIdx.x & 1, mt = blockIdx.x >> 1;
    const int m0 = mt * GXM, n0 = nblk * GXN;

    // bias
    for (int c = tid; c < GXN; c += 256) {
        int j = n0 + c;
        ((float*)(sm + SMX_BIAS))[c] = (j < G4) ? b_ih[j] + b_hh[j] : 0.f;
    }
    // cp.async A (E hi/lo): 128 rows x 14 units x 2 arrays
    for (int e = tid; e < 3584; e += 256) {
        int arr = e >= 1792, r = (e - arr * 1792) / 14, c = e % 14;
        const __half* src = (arr ? gE_lo : gE_hi) + (size_t)(m0 + r) * KP + c * 8;
        cp16(sb + SMX_A + arr * 30720 + r * ROWB + c * 16, src);
    }
    // cp.async B (Wih hi/lo): 224 rows x 14 x 2
    for (int e = tid; e < 6272; e += 256) {
        int arr = e >= 3136, r = (e - arr * 3136) / 14, c = e % 14;
        const __half* src = (arr ? gWih_lo : gWih_hi) + (size_t)(n0 + r) * KP + c * 8;
        cp16(sb + SMX_B + arr * 53760 + r * ROWB + c * 16, src);
    }
    asm volatile("cp.async.commit_group;");
    asm volatile("cp.async.wait_group 0;");
    __syncthreads();

    const int wid = tid >> 5, lane = tid & 31;
    const int wm = wid >> 2, wn = wid & 3;
    const int gid = lane >> 2, tig = lane & 3;
    const uint32_t* A32 = (const uint32_t*)(sm + SMX_A);
    const uint32_t* B32 = (const uint32_t*)(sm + SMX_B);

    float acc[4][7][4];
    #pragma unroll
    for (int mb = 0; mb < 4; mb++)
        #pragma unroll
        for (int nb = 0; nb < 7; nb++)
            #pragma unroll
            for (int q = 0; q < 4; q++) acc[mb][nb][q] = 0.f;

    #pragma unroll 1
    for (int ks = 0; ks < 7; ks++) {
        uint32_t ah[4][4], al[4][4];
        #pragma unroll
        for (int mb = 0; mb < 4; mb++) {
            int w = (wm * 64 + mb * 16 + gid) * ROWW + ks * 8 + tig;
            ah[mb][0] = A32[w];            al[mb][0] = A32[w + 7680];
            ah[mb][1] = A32[w + 8 * ROWW]; al[mb][1] = A32[w + 7680 + 8 * ROWW];
            ah[mb][2] = A32[w + 4];        al[mb][2] = A32[w + 7680 + 4];
            ah[mb][3] = A32[w + 8 * ROWW + 4];
            al[mb][3] = A32[w + 7680 + 8 * ROWW + 4];
        }
        #pragma unroll
        for (int nb = 0; nb < 7; nb++) {
            int w = (wn * 56 + nb * 8 + gid) * ROWW + ks * 8 + tig;
            uint32_t bh0 = B32[w], bh1 = B32[w + 4];
            uint32_t bl0 = B32[w + 13440], bl1 = B32[w + 13440 + 4];
            #pragma unroll
            for (int mb = 0; mb < 4; mb++) {
                mma_fp16(acc[mb][nb], ah[mb], bh0, bh1);
                mma_fp16(acc[mb][nb], ah[mb], bl0, bl1);
                mma_fp16(acc[mb][nb], al[mb], bh0, bh1);
            }
        }
    }

    const float* biasS = (const float*)(sm + SMX_BIAS);
    #pragma unroll
    for (int nb = 0; nb < 7; nb++) {
        int jl = wn * 56 + nb * 8 + tig * 2;
        int j  = n0 + jl;
        if (j < G4) {
            float b0 = biasS[jl], b1 = biasS[jl + 1];
            #pragma unroll
            for (int mb = 0; mb < 4; mb++) {
                int row = m0 + wm * 64 + mb * 16 + gid;
                *(float2*)(g_gx + (size_t)row * G4 + j) =
                    make_float2(acc[mb][nb][0] + b0, acc[mb][nb][1] + b1);
                *(float2*)(g_gx + (size_t)(row + 8) * G4 + j) =
                    make_float2(acc[mb][nb][2] + b0, acc[mb][nb][3] + b1);
            }
        }
    }
}

// ---------------------------------------------------------------------------
// Kernel 2: LSTM recurrence (unchanged — precision is load-bearing)
// ---------------------------------------------------------------------------
__device__ __forceinline__ void fma2(unsigned long long& acc,
                                     unsigned long long a,
                                     unsigned long long b) {
    asm("fma.rn.f32x2 %0, %1, %2, %0;" : "+l"(acc) : "l"(a), "l"(b));
}
__device__ __forceinline__ float unpack_sum(unsigned long long a) {
    float lo, hi;
    asm("mov.b64 {%0, %1}, %2;" : "=f"(lo), "=f"(hi) : "l"(a));
    return lo + hi;
}

__global__ __launch_bounds__(416, 1) void lstm_kernel(const float* __restrict__ W_hh) {
    __shared__ __align__(16) float h_s[HID];
    __shared__ float acts[G4];
    const int j = threadIdx.x;
    const int b = blockIdx.x;

    unsigned long long w2[50];
    if (j < G4) {
        const unsigned long long* wg =
            (const unsigned long long*)(W_hh + (size_t)j * HID);
        #pragma unroll
        for (int k = 0; k < 50; k++) w2[k] = wg[k];
    }
    if (j < HID) h_s[j] = 0.f;
    float c = 0.f;
    float gcur = (j < G4) ? g_gx[(size_t)b * G4 + j] : 0.f;
    __syncthreads();

    for (int t = 0; t < T_STEPS; t++) {
        float gnext = 0.f;
        if (t + 1 < T_STEPS && j < G4)
            gnext = g_gx[((size_t)(t + 1) * BATCH + b) * G4 + j];

        float a = 0.f;
        if (j < G4) {
            const unsigned long long* h2 = (const unsigned long long*)h_s;
            unsigned long long acc0 = 0ull, acc1 = 0ull;
            #pragma unroll
            for (int k = 0; k < 50; k += 2) {
                fma2(acc0, w2[k],     h2[k]);
                fma2(acc1, w2[k + 1], h2[k + 1]);
            }
            float d = gcur + unpack_sum(acc0) + unpack_sum(acc1);
            if (j >= 2 * HID && j < 3 * HID) a = tanhf(d);
            else                             a = 1.f / (1.f + expf(-d));
            acts[j] = a;
        }
        __syncthreads();

        if (j < HID) {
            float ig = acts[j], fg = acts[HID + j];
            float gg = acts[2 * HID + j], og = acts[3 * HID + j];
            c = fg * c + ig * gg;
            float hn = og * tanhf(c);
            h_s[j] = hn;
            g_hs[((size_t)t * BATCH + b) * HID + j] = hn;
        }
        __syncthreads();
        gcur = gnext;
    }
}

// ---------------------------------------------------------------------------
// Kernel 3: splitA — g_hs -> gA hi/lo fp16. Also resets work-steal counter.
// ---------------------------------------------------------------------------
#define A_UNITS (M_ROWS * 14)   // 57344 = 224 * 256

__global__ __launch_bounds__(256) void splitA_kernel() {
    if (blockIdx.x == 0 && threadIdx.x == 0) g_counter = 0;
    const int u = blockIdx.x * 256 + threadIdx.x;
    int row = u / 14, k0 = (u % 14) * 8;
    float v[8];
    #pragma unroll
    for (int i = 0; i < 8; i++) {
        int k = k0 + i;
        v[i] = (k < HID) ? g_hs[(size_t)row * HID + k] : 0.f;
    }
    uint32_t ph[4], pl[4];
    split8(v, ph, pl);
    size_t d = (size_t)row * KP + k0;
    *(uint4*)(gA_hi + d) = make_uint4(ph[0], ph[1], ph[2], ph[3]);
    *(uint4*)(gA_lo + d) = make_uint4(pl[0], pl[1], pl[2], pl[3]);
}

// ---------------------------------------------------------------------------
// Kernel 4: vocab GEMM. 2-term fp16 (ah·bh + al·bh). 64x192 tiles,
// 128 threads, 2 CTAs/SM, B-stationary segments of 4 m-tiles, work-stealing.
// 4 warps 1(M)x4(N); warp tile 64x48.
// ---------------------------------------------------------------------------
#define SMG_BIAS 0                     // 192 floats
#define SMG_SEG  768
#define SMG_A    1024                  // buf: hi 15360 + lo 15360; x2 bufs
#define SMG_B    (SMG_A + 2 * 30720)   // 62464: hi only, 192x240 = 46080
#define SMG_TOT  (SMG_B + NT * ROWB)   // 108544

__global__ __launch_bounds__(128, 2) void gemm_kernel(
        const float* __restrict__ out_b, float* __restrict__ out) {
    extern __shared__ char sm[];
    const uint32_t sb = smem_u32(sm);
    const int tid = threadIdx.x;
    const int wid = tid >> 5, lane = tid & 31;
    const int wn  = wid;                       // 1x4 warp grid
    const int gid = lane >> 2, tig = lane & 3;

    for (;;) {
        if (tid == 0) *(int*)(sm + SMG_SEG) = atomicAdd(&g_counter, 1);
        __syncthreads();
        const int seg = *(const int*)(sm + SMG_SEG);
        if (seg >= NSEG) break;
        const int n0  = (seg >> 4) * NT;
        const int mt0 = (seg & 15) * SEG_M;    // m-tile index (64-row tiles)

        // bias
        for (int c = tid; c < NT; c += 128) {
            int col = n0 + c;
            ((float*)(sm + SMG_BIAS))[c] = (col < VOCAB) ? out_b[col] : 0.f;
        }
        // B (hi only): 192 rows x 14 units
        for (int e = tid; e < 2688; e += 128) {
            int r = e / 14, c = e % 14;
            cp16(sb + SMG_B + r * ROWB + c * 16,
                 gW_hi + (size_t)(n0 + r) * KP + c * 8);
        }
        // A tile 0 (hi+lo): 64 rows x 14 x 2
        {
            const int m0 = mt0 * MT;
            for (int e = tid; e < 1792; e += 128) {
                int arr = e >= 896, r = (e - arr * 896) / 14, c = e % 14;
                cp16(sb + SMG_A + arr * 15360 + r * ROWB + c * 16,
                     (arr ? gA_lo : gA_hi) + (size_t)(m0 + r) * KP + c * 8);
            }
        }
        asm volatile("cp.async.commit_group;");
        asm volatile("cp.async.wait_group 0;");
        __syncthreads();

        #pragma unroll 1
        for (int it = 0; it < SEG_M; it++) {
            if (it < SEG_M - 1) {
                const int m1 = (mt0 + it + 1) * MT;
                const uint32_t abase = sb + SMG_A + ((it + 1) & 1) * 30720;
                for (int e = tid; e < 1792; e += 128) {
                    int arr = e >= 896, r = (e - arr * 896) / 14, c = e % 14;
                    cp16(abase + arr * 15360 + r * ROWB + c * 16,
                         (arr ? gA_lo : gA_hi) + (size_t)(m1 + r) * KP + c * 8);
                }
                asm volatile("cp.async.commit_group;");
            }

            const uint32_t* A32 = (const uint32_t*)(sm + SMG_A + (it & 1) * 30720);
            const uint32_t* B32 = (const uint32_t*)(sm + SMG_B);

            float acc[4][6][4];
            #pragma unroll
            for (int mb = 0; mb < 4; mb++)
                #pragma unroll
                for (int nb = 0; nb < 6; nb++)
                    #pragma unroll
                    for (int q = 0; q < 4; q++) acc[mb][nb][q] = 0.f;

            #pragma unroll 1
            for (int ks = 0; ks < 7; ks++) {
                uint32_t ah[4][4], al[4][4];
                #pragma unroll
                for (int mb = 0; mb < 4; mb++) {
                    int w = (mb * 16 + gid) * ROWW + ks * 8 + tig;
                    ah[mb][0] = A32[w];            al[mb][0] = A32[w + 3840];
                    ah[mb][1] = A32[w + 8 * ROWW]; al[mb][1] = A32[w + 3840 + 8 * ROWW];
                    ah[mb][2] = A32[w + 4];        al[mb][2] = A32[w + 3840 + 4];
                    ah[mb][3] = A32[w + 8 * ROWW + 4];
                    al[mb][3] = A32[w + 3840 + 8 * ROWW + 4];
                }
                #pragma unroll
                for (int nb = 0; nb < 6; nb++) {
                    int w = (wn * 48 + nb * 8 + gid) * ROWW + ks * 8 + tig;
                    uint32_t bh0 = B32[w], bh1 = B32[w + 4];
                    #pragma unroll
                    for (int mb = 0; mb < 4; mb++) {
                        mma_fp16(acc[mb][nb], ah[mb], bh0, bh1);
                        mma_fp16(acc[mb][nb], al[mb], bh0, bh1);
                    }
                }
            }

            const int m0 = (mt0 + it) * MT;
            const float* biasS = (const float*)(sm + SMG_BIAS);
            #pragma unroll
            for (int nb = 0; nb < 6; nb++) {
                int cl  = wn * 48 + nb * 8 + tig * 2;
                int col = n0 + cl;
                if (col < VOCAB) {
                    float b0 = biasS[cl], b1 = biasS[cl + 1];
                    #pragma unroll
                    for (int mb = 0; mb < 4; mb++) {
                        int row = m0 + mb * 16 + gid;
                        *(float2*)(out + (size_t)row * VOCAB + col) =
                            make_float2(acc[mb][nb][0] + b0, acc[mb][nb][1] + b1);
                        *(float2*)(out + (size_t)(row + 8) * VOCAB + col) =
                            make_float2(acc[mb][nb][2] + b0, acc[mb][nb][3] + b1);
                    }
                }
            }

            if (it < SEG_M - 1) asm volatile("cp.async.wait_group 0;");
            __syncthreads();
        }
    }
}

// ---------------------------------------------------------------------------
// Launch. Inputs: 0 input, 1 emb, 2..5 enc_* (dead), 6 dec_W_ih, 7 dec_W_hh,
// 8 dec_b_ih, 9 dec_b_hh, 10 out_W, 11 out_b.
// ---------------------------------------------------------------------------
extern "C" void kernel_launch(void* const* d_in, const int* in_sizes, int n_in,
                              void* d_out, int out_size) {
    (void)in_sizes; (void)n_in; (void)out_size;
    const int*   input = (const int*)d_in[0];
    const float* emb   = (const float*)d_in[1];
    const float* dWih  = (const float*)d_in[6];
    const float* dWhh  = (const float*)d_in[7];
    const float* dbih  = (const float*)d_in[8];
    const float* dbhh  = (const float*)d_in[9];
    const float* outW  = (const float*)d_in[10];
    const float* outb  = (const float*)d_in[11];
    float* out = (float*)d_out;

    cudaFuncSetAttribute(gx_mma_kernel,
                         cudaFuncAttributeMaxDynamicSharedMemorySize, SMX_TOT);
    cudaFuncSetAttribute(gemm_kernel,
                         cudaFuncAttributeMaxDynamicSharedMemorySize, SMG_TOT);

    presplit_kernel<<<U_TOT / 256, 256>>>(input, emb, dWih, outW);
    gx_mma_kernel<<<64, 256, SMX_TOT>>>(dbih, dbhh);
    lstm_kernel<<<BATCH, 416>>>(dWhh);
    splitA_kernel<<<A_UNITS / 256, 256>>>();
    gemm_kernel<<<296, 128, SMG_TOT>>>(outb, out);
}